// round 15
// baseline (speedup 1.0000x reference)
#include <cuda_runtime.h>
#include <cuda_fp16.h>
#include <cstdint>

#define N_NODES 100000
#define N_EDGES 625000
#define D_IN    128
#define D_HID   256
#define NSCAN   100352        // 392 * 256 >= N_NODES + 1
#define NBLK    392

// ---------------------------------------------------------------------------
// Scratch (__device__ globals; allocation-free rule)
// ---------------------------------------------------------------------------
__device__ int    g_off[NSCAN];        // CSR offsets (exclusive prefix)
__device__ int    g_bsum[NBLK];        // scan block totals
__device__ int    g_cur[N_NODES];      // scatter cursors
__device__ int    g_csr[N_EDGES];      // CSR adjacency (src per slot)
__device__ __half g_xh[(size_t)N_NODES * D_IN];     // x converted to fp16
// Weight image W_cat^T SWAPPED: [n (256)][k (256)] fp16 (512B rows).
// k<128 -> w_r[k][n] (pairs with x), k>=128 -> w_l[k-128][n] (pairs with mean).
__device__ __half g_Wh[256 * 256];

// ---------------------------------------------------------------------------
// Kernel I: fused init — xconv (blocks 0..12499), prep (12500..12597),
// wconv (12598..12853)
// ---------------------------------------------------------------------------
__global__ void init_kernel(const float* __restrict__ x,
                            const float* __restrict__ wl,
                            const float* __restrict__ wr) {
    int b = blockIdx.x;
    int tid = threadIdx.x;
    if (b < 12500) {                       // xconv: 3,200,000 float4
        int i = b * 256 + tid;
        float4 v = ((const float4*)x)[i];
        __half2 h01 = __floats2half2_rn(v.x, v.y);
        __half2 h23 = __floats2half2_rn(v.z, v.w);
        uint2 u;
        u.x = *reinterpret_cast<uint32_t*>(&h01);
        u.y = *reinterpret_cast<uint32_t*>(&h23);
        ((uint2*)g_xh)[i] = u;
    } else if (b < 12598) {                // prep: zero g_off (25,088 int4)
        int i = (b - 12500) * 256 + tid;
        ((int4*)g_off)[i] = make_int4(0, 0, 0, 0);
    } else {                               // wconv: 65,536 elems (halves swapped)
        int idx = (b - 12598) * 256 + tid;
        int n = idx >> 8;
        int k = idx & 255;
        float v = (k < 128) ? wr[k * 256 + n] : wl[(k - 128) * 256 + n];
        g_Wh[idx] = __float2half_rn(v);
    }
}

// ---------------------------------------------------------------------------
// Kernel P1: degree histogram into g_off[dst+1]
// ---------------------------------------------------------------------------
__global__ void hist_kernel(const int* __restrict__ ei) {
    int e = blockIdx.x * blockDim.x + threadIdx.x;
    if (e < N_EDGES)
        atomicAdd(&g_off[ei[N_EDGES + e] + 1], 1);
}

// ---------------------------------------------------------------------------
// Kernel P2a: per-block inclusive scan (256 elems/block); store block totals
// ---------------------------------------------------------------------------
__global__ void scan_block_kernel() {
    __shared__ int s[256];
    int tid = threadIdx.x;
    int i = blockIdx.x * 256 + tid;
    s[tid] = g_off[i];
#pragma unroll
    for (int off = 1; off < 256; off <<= 1) {
        __syncthreads();
        int tmp = (tid >= off) ? s[tid - off] : 0;
        __syncthreads();
        s[tid] += tmp;
    }
    __syncthreads();
    g_off[i] = s[tid];
    if (tid == 255) g_bsum[blockIdx.x] = s[255];
}

// ---------------------------------------------------------------------------
// Kernel P2b: add block prefix (reduced locally from g_bsum); init cursors
// ---------------------------------------------------------------------------
__global__ void scan_add_kernel() {
    __shared__ int ssum[256];
    int tid = threadIdx.x;
    int b = blockIdx.x;

    int v = 0;
    for (int j = tid; j < b; j += 256) v += g_bsum[j];
    ssum[tid] = v;
#pragma unroll
    for (int off = 128; off > 0; off >>= 1) {
        __syncthreads();
        if (tid < off) ssum[tid] += ssum[tid + off];
    }
    __syncthreads();
    int add = ssum[0];

    int i = b * 256 + tid;
    int val = g_off[i] + add;
    g_off[i] = val;
    if (i < N_NODES) g_cur[i] = val;
}

// ---------------------------------------------------------------------------
// Kernel P3: scatter edges into CSR slots
// ---------------------------------------------------------------------------
__global__ void scatter_kernel(const int* __restrict__ ei) {
    int e = blockIdx.x * blockDim.x + threadIdx.x;
    if (e < N_EDGES) {
        int src = ei[e];
        int dst = ei[N_EDGES + e];
        int idx = atomicAdd(&g_cur[dst], 1);
        g_csr[idx] = src;
    }
}

// ---------------------------------------------------------------------------
// PTX helpers (family-portable: sm_75/80+)
// ---------------------------------------------------------------------------
__device__ __forceinline__ uint32_t smem_u32(const void* p) {
    uint32_t a;
    asm("{ .reg .u64 t; cvta.to.shared.u64 t, %1; cvt.u32.u64 %0, t; }"
        : "=r"(a) : "l"(p));
    return a;
}
__device__ __forceinline__ void mma_f16(float* d, const uint32_t* a,
                                        uint32_t b0, uint32_t b1) {
    asm volatile(
        "mma.sync.aligned.m16n8k16.row.col.f32.f16.f16.f32 "
        "{%0,%1,%2,%3}, {%4,%5,%6,%7}, {%8,%9}, {%0,%1,%2,%3};"
        : "+f"(d[0]), "+f"(d[1]), "+f"(d[2]), "+f"(d[3])
        : "r"(a[0]), "r"(a[1]), "r"(a[2]), "r"(a[3]), "r"(b0), "r"(b1));
}
#define LDSM4(d0, d1, d2, d3, addr) \
    asm volatile("ldmatrix.sync.aligned.m8n8.x4.shared.b16 {%0,%1,%2,%3}, [%4];" \
        : "=r"(d0), "=r"(d1), "=r"(d2), "=r"(d3) : "r"(addr))
#define CPASYNC16(dst, src) \
    asm volatile("cp.async.ca.shared.global [%0], [%1], 16;" :: "r"(dst), "l"(src))
#define CPCOMMIT() asm volatile("cp.async.commit_group;" ::: "memory")
#define CPWAIT0()  asm volatile("cp.async.wait_group 0;" ::: "memory")

// ---------------------------------------------------------------------------
// Kernel N: fp16 1-pass mma.sync node kernel with FUSED gather-aggregation.
// Chunks 0-1: A = x (cp.async from g_xh), B = wr columns.
// Chunks 2-3: A = mean (gathered into s_agg smem during chunk 0), B = wl.
// Block = 256 threads (8 warps), M=64 nodes, N=256, warp tile M32 x N64.
//
// SMEM/CTA (111,616 B -> 2 CTAs/SM):
//   A bufs [2 buf][64 rows][72 halfs]  @ 0        (18,432)
//   B bufs [2 buf][256 rows][72 halfs] @ 18,432   (73,728)
//   s_agg [2 kc][64 rows][72 halfs]    @ 92,160   (18,432)
//   s_bl [256] f32                     @ 110,592
//   epilogue overlays: s_part 16K @0; s_wh @16,384; s_bh @33,792
// ---------------------------------------------------------------------------
#define AST     144           // bytes per smem row (64 halfs + 16B pad)
#define A_IMG   9216          // 64*144
#define B_OFF   18432
#define B_IMG   36864         // 256*144
#define AGG_OFF 92160
#define OFF_BL  110592
#define SMEM_DYN 111616
#define E_WH  16384
#define E_BH  33792

__global__ __launch_bounds__(256, 2) void node_mma_kernel(
    const float* __restrict__ wp, const float* __restrict__ bp,
    const float* __restrict__ ws, const float* __restrict__ bs,
    const float* __restrict__ bl,
    float* __restrict__ out)
{
    extern __shared__ float4 smem4[];
    char* smem = (char*)smem4;
    const uint32_t sb = smem_u32(smem);
    float* s_bl = (float*)(smem + OFF_BL);

    const int t    = threadIdx.x;
    const int w    = t >> 5;
    const int lane = t & 31;
    const int lq   = lane >> 2;
    const int lr   = (lane & 3) * 2;
    const long long base = (long long)blockIdx.x * 64;

    if (t < 256) s_bl[t] = bl[t];

    const int m0    = (w & 1) * 32;    // 2 M-strips
    const int nbase = (w >> 1) * 64;   // 4 N-strips

    float acc[64];
#pragma unroll
    for (int i = 0; i < 64; i++) acc[i] = 0.f;

    // ---- staging helpers (k=64 chunks) ----
    auto stageB = [&](int c, int buf) {   // 256 rows x 128B, cp.async
        const char* gs = (const char*)&g_Wh[0];
#pragma unroll
        for (int it = 0; it < 8; it++) {
            int i = t + it * 256;
            int n = i >> 3, q = i & 7;
            uint32_t dst = sb + B_OFF + buf * B_IMG + n * AST + q * 16;
            CPASYNC16(dst, gs + n * 512 + c * 128 + q * 16);
        }
    };
    auto stageA_x = [&](int c, int buf) {   // x rows via cp.async (c = 0 or 1)
        int koff = c * 64;
#pragma unroll
        for (int it = 0; it < 2; it++) {
            int i = t + it * 256;
            int m = i >> 3, q = i & 7;
            long long node = base + m;
            if (node >= N_NODES) node = N_NODES - 1;
            uint32_t dst = sb + buf * A_IMG + m * AST + q * 16;
            CPASYNC16(dst, (const char*)(g_xh + node * D_IN + koff) + q * 16);
        }
    };
    auto stageA_agg = [&](int c, int buf) {   // smem->smem copy (c = 2 or 3)
        const char* src = smem + AGG_OFF + (c - 2) * A_IMG;
        char* dst = smem + buf * A_IMG;
#pragma unroll
        for (int it = 0; it < 2; it++) {
            int i = t + it * 256;
            int m = i >> 3, q = i & 7;
            *(uint4*)(dst + m * AST + q * 16) = *(const uint4*)(src + m * AST + q * 16);
        }
    };

    // ---- prologue: chunk 0 (x, k 0-63) into buffer 0 ----
    stageB(0, 0);
    stageA_x(0, 0);
    CPCOMMIT();
    CPWAIT0();
    __syncthreads();

    const int tt    = lane >> 3;
    const int arow  = ((tt & 1) * 8) + (lane & 7);
    const int acol2 = ((tt >> 1) * 8) * 2;

    // ---- mainloop: 4 chunks ----
    for (int c = 0; c < 4; c++) {
        int cur = c & 1, nxt = cur ^ 1;
        if (c < 3) {
            stageB(c + 1, nxt);
            if (c == 0) stageA_x(1, nxt);
            else        stageA_agg(c + 1, nxt);
            CPCOMMIT();
        }

        // Fused gather during chunk 0: warp gathers its 8 nodes' neighbor
        // means into s_agg (A-image layout). Done before c=1's sync, which
        // is all stageA_agg needs.
        if (c == 0) {
#pragma unroll 1
            for (int r = 0; r < 8; r++) {
                int m = w * 8 + r;
                long long node = base + m;
                if (node >= N_NODES) node = N_NODES - 1;
                int beg = g_off[node], end = g_off[node + 1];
                float a0 = 0.f, a1 = 0.f, a2 = 0.f, a3 = 0.f;
                int s_next = (beg < end) ? g_csr[beg] : 0;
                for (int e = beg; e < end; e++) {
                    int s_cur = s_next;
                    if (e + 1 < end) s_next = g_csr[e + 1];
                    uint2 u = *(const uint2*)(g_xh + (long long)s_cur * D_IN + lane * 4);
                    __half2 h01 = *reinterpret_cast<__half2*>(&u.x);
                    __half2 h23 = *reinterpret_cast<__half2*>(&u.y);
                    float2 f01 = __half22float2(h01);
                    float2 f23 = __half22float2(h23);
                    a0 += f01.x; a1 += f01.y; a2 += f23.x; a3 += f23.y;
                }
                float inv = (end > beg) ? 1.f / (float)(end - beg) : 0.f;
                __half2 h01 = __floats2half2_rn(a0 * inv, a1 * inv);
                __half2 h23 = __floats2half2_rn(a2 * inv, a3 * inv);
                uint2 u;
                u.x = *reinterpret_cast<uint32_t*>(&h01);
                u.y = *reinterpret_cast<uint32_t*>(&h23);
                int kc = lane >> 4;                 // 0: k 0-63, 1: k 64-127
                *(uint2*)(smem + AGG_OFF + kc * A_IMG + m * AST + (lane & 15) * 8) = u;
            }
        }

        const uint32_t Ab = sb + cur * A_IMG;
        const uint32_t Bb = sb + B_OFF + cur * B_IMG;
#pragma unroll
        for (int ks = 0; ks < 4; ks++) {
            int kb = ks * 32;
            uint32_t a0[4], a1[4], b[4][4];
            uint32_t ad = Ab + (m0 + arow) * AST + kb + acol2;
            LDSM4(a0[0], a0[1], a0[2], a0[3], ad);
            LDSM4(a1[0], a1[1], a1[2], a1[3], ad + 16 * AST);
#pragma unroll
            for (int j = 0; j < 4; j++) {
                uint32_t bd = Bb + (nbase + j * 16 + arow) * AST + kb + acol2;
                LDSM4(b[j][0], b[j][1], b[j][2], b[j][3], bd);
            }
#pragma unroll
            for (int j = 0; j < 4; j++) {
                int nt0 = j * 2, nt1 = j * 2 + 1;
                mma_f16(acc + nt0 * 4,      a0, b[j][0], b[j][2]);
                mma_f16(acc + nt1 * 4,      a0, b[j][1], b[j][3]);
                mma_f16(acc + 32 + nt0 * 4, a1, b[j][0], b[j][2]);
                mma_f16(acc + 32 + nt1 * 4, a1, b[j][1], b[j][3]);
            }
        }
        if (c < 3) CPWAIT0();
        __syncthreads();
    }

    // ---- epilogue: overlay A/B region (register-resident heads) ----
    float* s_part = (float*)smem;              // [4 nstrip][64 m][16]
    float* s_wh   = (float*)(smem + E_WH);     // [256][17]
    float* s_bh   = (float*)(smem + E_BH);

    for (int i = t; i < 13 * 256; i += 256) {
        int j = i & 255, cc = i >> 8;
        s_wh[j * 17 + cc] = (cc < 7) ? wp[j * 7 + cc] : ws[j * 6 + (cc - 7)];
    }
    if (t < 16) s_bh[t] = (t < 7) ? bp[t] : (t < 13 ? bs[t - 7] : 0.f);
    __syncthreads();

    const int nstrip = w >> 1;
#pragma unroll
    for (int mi = 0; mi < 2; mi++) {
        float pr0[13], pr1[13];
#pragma unroll
        for (int cc = 0; cc < 13; cc++) { pr0[cc] = 0.f; pr1[cc] = 0.f; }
#pragma unroll
        for (int nt = 0; nt < 8; nt++) {
            int col0 = nbase + nt * 8 + lr;
            float b0 = s_bl[col0], b1 = s_bl[col0 + 1];
            const float* d = acc + mi * 32 + nt * 4;
            float h00 = fmaxf(d[0] + b0, 0.f), h01 = fmaxf(d[1] + b1, 0.f);
            float h10 = fmaxf(d[2] + b0, 0.f), h11 = fmaxf(d[3] + b1, 0.f);
            const float* w0 = s_wh + col0 * 17;
            const float* w1 = w0 + 17;
#pragma unroll
            for (int cc = 0; cc < 13; cc++) {
                float wa = w0[cc], wb = w1[cc];
                pr0[cc] = fmaf(h00, wa, fmaf(h01, wb, pr0[cc]));
                pr1[cc] = fmaf(h10, wa, fmaf(h11, wb, pr1[cc]));
            }
        }
#pragma unroll
        for (int cc = 0; cc < 13; cc++) {
            pr0[cc] += __shfl_xor_sync(0xffffffff, pr0[cc], 1);
            pr0[cc] += __shfl_xor_sync(0xffffffff, pr0[cc], 2);
            pr1[cc] += __shfl_xor_sync(0xffffffff, pr1[cc], 1);
            pr1[cc] += __shfl_xor_sync(0xffffffff, pr1[cc], 2);
        }
        if ((lane & 3) == 0) {
            int r = m0 + mi * 16 + lq;
#pragma unroll
            for (int cc = 0; cc < 13; cc++) {
                s_part[nstrip * 1024 + r * 16 + cc]       = pr0[cc];
                s_part[nstrip * 1024 + (r + 8) * 16 + cc] = pr1[cc];
            }
        }
    }
    __syncthreads();

    // final reduce + log_softmax + writeout
    if (t < 64) {
        long long node = base + t;
        if (node < N_NODES) {
            float o[13];
#pragma unroll
            for (int cc = 0; cc < 13; cc++) {
                o[cc] = s_bh[cc] + s_part[t * 16 + cc] + s_part[1024 + t * 16 + cc]
                      + s_part[2048 + t * 16 + cc] + s_part[3072 + t * 16 + cc];
            }
            float mx = o[0];
#pragma unroll
            for (int cc = 1; cc < 7; cc++) mx = fmaxf(mx, o[cc]);
            float s = 0.f;
#pragma unroll
            for (int cc = 0; cc < 7; cc++) s += __expf(o[cc] - mx);
            float lse = mx + __logf(s);
#pragma unroll
            for (int cc = 0; cc < 7; cc++) out[node * 7 + cc] = o[cc] - lse;

            mx = o[7];
#pragma unroll
            for (int cc = 8; cc < 13; cc++) mx = fmaxf(mx, o[cc]);
            s = 0.f;
#pragma unroll
            for (int cc = 7; cc < 13; cc++) s += __expf(o[cc] - mx);
            lse = mx + __logf(s);
            float* out2 = out + (long long)N_NODES * 7;
#pragma unroll
            for (int cc = 0; cc < 6; cc++) out2[node * 6 + cc] = o[7 + cc] - lse;
        }
    }
}

// ---------------------------------------------------------------------------
extern "C" void kernel_launch(void* const* d_in, const int* in_sizes, int n_in,
                              void* d_out, int out_size) {
    const float* x  = (const float*)d_in[0];
    const int*   ei = (const int*)d_in[1];
    const float* wl = (const float*)d_in[2];
    const float* bl = (const float*)d_in[3];
    const float* wr = (const float*)d_in[4];
    const float* wp = (const float*)d_in[5];
    const float* bp = (const float*)d_in[6];
    const float* ws = (const float*)d_in[7];
    const float* bs = (const float*)d_in[8];
    float* out = (float*)d_out;

    cudaFuncSetAttribute(node_mma_kernel,
                         cudaFuncAttributeMaxDynamicSharedMemorySize, SMEM_DYN);

    init_kernel<<<12854, 256>>>(x, wl, wr);
    hist_kernel<<<(N_EDGES + 255) / 256, 256>>>(ei);
    scan_block_kernel<<<NBLK, 256>>>();
    scan_add_kernel<<<NBLK, 256>>>();
    scatter_kernel<<<(N_EDGES + 255) / 256, 256>>>(ei);

    int node_blocks = (N_NODES + 63) / 64;   // 1563
    node_mma_kernel<<<node_blocks, 256, SMEM_DYN>>>(wp, bp, ws, bs, bl, out);
}

// round 16
// speedup vs baseline: 1.1862x; 1.1862x over previous
#include <cuda_runtime.h>
#include <cuda_fp16.h>
#include <cstdint>

#define N_NODES 100000
#define N_EDGES 625000
#define D_IN    128
#define D_HID   256
#define NSCAN   100352        // 392 * 256 >= N_NODES + 1
#define NBLK    392

// ---------------------------------------------------------------------------
// Scratch (__device__ globals; allocation-free rule)
// ---------------------------------------------------------------------------
__device__ int    g_off[NSCAN];        // CSR offsets (exclusive prefix)
__device__ int    g_bsum[NBLK];        // scan block totals
__device__ int    g_cur[N_NODES];      // scatter cursors
__device__ int    g_csr[N_EDGES];      // CSR adjacency (src per slot)
__device__ __half g_aggh[(size_t)N_NODES * D_IN];   // mean-aggregated, fp16
__device__ __half g_xh[(size_t)N_NODES * D_IN];     // x converted to fp16
// Weight image W_cat^T: [n (256)][k (256)] fp16 (512B rows).
// k<128 -> w_l[k][n], k>=128 -> w_r[k-128][n].
__device__ __half g_Wh[256 * 256];

// ---------------------------------------------------------------------------
// Kernel I: fused init — xconv (blocks 0..12499), prep (12500..12597),
// wconv (12598..12853)
// ---------------------------------------------------------------------------
__global__ void init_kernel(const float* __restrict__ x,
                            const float* __restrict__ wl,
                            const float* __restrict__ wr) {
    int b = blockIdx.x;
    int tid = threadIdx.x;
    if (b < 12500) {                       // xconv: 3,200,000 float4
        int i = b * 256 + tid;
        float4 v = ((const float4*)x)[i];
        __half2 h01 = __floats2half2_rn(v.x, v.y);
        __half2 h23 = __floats2half2_rn(v.z, v.w);
        uint2 u;
        u.x = *reinterpret_cast<uint32_t*>(&h01);
        u.y = *reinterpret_cast<uint32_t*>(&h23);
        ((uint2*)g_xh)[i] = u;
    } else if (b < 12598) {                // prep: zero g_off (25,088 int4)
        int i = (b - 12500) * 256 + tid;
        ((int4*)g_off)[i] = make_int4(0, 0, 0, 0);
    } else {                               // wconv: 65,536 elems
        int idx = (b - 12598) * 256 + tid;
        int n = idx >> 8;
        int k = idx & 255;
        float v = (k < 128) ? wl[k * 256 + n] : wr[(k - 128) * 256 + n];
        g_Wh[idx] = __float2half_rn(v);
    }
}

// ---------------------------------------------------------------------------
// Kernel P1: degree histogram into g_off[dst+1]
// ---------------------------------------------------------------------------
__global__ void hist_kernel(const int* __restrict__ ei) {
    int e = blockIdx.x * blockDim.x + threadIdx.x;
    if (e < N_EDGES)
        atomicAdd(&g_off[ei[N_EDGES + e] + 1], 1);
}

// ---------------------------------------------------------------------------
// Kernel P2a: per-block inclusive scan (256 elems/block); store block totals
// ---------------------------------------------------------------------------
__global__ void scan_block_kernel() {
    __shared__ int s[256];
    int tid = threadIdx.x;
    int i = blockIdx.x * 256 + tid;
    s[tid] = g_off[i];
#pragma unroll
    for (int off = 1; off < 256; off <<= 1) {
        __syncthreads();
        int tmp = (tid >= off) ? s[tid - off] : 0;
        __syncthreads();
        s[tid] += tmp;
    }
    __syncthreads();
    g_off[i] = s[tid];
    if (tid == 255) g_bsum[blockIdx.x] = s[255];
}

// ---------------------------------------------------------------------------
// Kernel P2b: add block prefix (reduced locally from g_bsum); init cursors
// ---------------------------------------------------------------------------
__global__ void scan_add_kernel() {
    __shared__ int ssum[256];
    int tid = threadIdx.x;
    int b = blockIdx.x;

    int v = 0;
    for (int j = tid; j < b; j += 256) v += g_bsum[j];
    ssum[tid] = v;
#pragma unroll
    for (int off = 128; off > 0; off >>= 1) {
        __syncthreads();
        if (tid < off) ssum[tid] += ssum[tid + off];
    }
    __syncthreads();
    int add = ssum[0];

    int i = b * 256 + tid;
    int val = g_off[i] + add;
    g_off[i] = val;
    if (i < N_NODES) g_cur[i] = val;
}

// ---------------------------------------------------------------------------
// Kernel P3: scatter edges into CSR slots
// ---------------------------------------------------------------------------
__global__ void scatter_kernel(const int* __restrict__ ei) {
    int e = blockIdx.x * blockDim.x + threadIdx.x;
    if (e < N_EDGES) {
        int src = ei[e];
        int dst = ei[N_EDGES + e];
        int idx = atomicAdd(&g_cur[dst], 1);
        g_csr[idx] = src;
    }
}

// ---------------------------------------------------------------------------
// Kernel P4: gather-aggregate (warp per node) from fp16 image g_xh.
// Warp-cooperative index fetch: one coalesced CSR load per <=32 neighbors,
// then shfl-broadcast; row loads issue with full MLP (no dependent chain).
// ---------------------------------------------------------------------------
__global__ void gather_kernel() {
    int n    = blockIdx.x * 8 + (threadIdx.x >> 5);   // 12500*8 = 100000
    int lane = threadIdx.x & 31;

    int beg = g_off[n], end = g_off[n + 1];
    int d = end - beg;
    float a0 = 0.f, a1 = 0.f, a2 = 0.f, a3 = 0.f;

    for (int b0 = 0; b0 < d; b0 += 32) {
        int cnt = min(32, d - b0);
        int idx = (lane < cnt) ? g_csr[beg + b0 + lane] : 0;
#pragma unroll 4
        for (int j = 0; j < cnt; j++) {
            int s = __shfl_sync(0xffffffff, idx, j);
            uint2 u = *(const uint2*)(g_xh + (long long)s * D_IN + lane * 4);
            __half2 h01 = *reinterpret_cast<__half2*>(&u.x);
            __half2 h23 = *reinterpret_cast<__half2*>(&u.y);
            float2 f01 = __half22float2(h01);
            float2 f23 = __half22float2(h23);
            a0 += f01.x; a1 += f01.y; a2 += f23.x; a3 += f23.y;
        }
    }
    float inv = (d > 0) ? 1.f / (float)d : 0.f;
    __half2 h01 = __floats2half2_rn(a0 * inv, a1 * inv);
    __half2 h23 = __floats2half2_rn(a2 * inv, a3 * inv);
    uint2 u;
    u.x = *reinterpret_cast<uint32_t*>(&h01);
    u.y = *reinterpret_cast<uint32_t*>(&h23);
    *(uint2*)(g_aggh + (long long)n * D_IN + lane * 4) = u;
}

// ---------------------------------------------------------------------------
// PTX helpers (family-portable: sm_75/80+)
// ---------------------------------------------------------------------------
__device__ __forceinline__ uint32_t smem_u32(const void* p) {
    uint32_t a;
    asm("{ .reg .u64 t; cvta.to.shared.u64 t, %1; cvt.u32.u64 %0, t; }"
        : "=r"(a) : "l"(p));
    return a;
}
__device__ __forceinline__ void mma_f16(float* d, const uint32_t* a,
                                        uint32_t b0, uint32_t b1) {
    asm volatile(
        "mma.sync.aligned.m16n8k16.row.col.f32.f16.f16.f32 "
        "{%0,%1,%2,%3}, {%4,%5,%6,%7}, {%8,%9}, {%0,%1,%2,%3};"
        : "+f"(d[0]), "+f"(d[1]), "+f"(d[2]), "+f"(d[3])
        : "r"(a[0]), "r"(a[1]), "r"(a[2]), "r"(a[3]), "r"(b0), "r"(b1));
}
#define LDSM4(d0, d1, d2, d3, addr) \
    asm volatile("ldmatrix.sync.aligned.m8n8.x4.shared.b16 {%0,%1,%2,%3}, [%4];" \
        : "=r"(d0), "=r"(d1), "=r"(d2), "=r"(d3) : "r"(addr))
#define CPASYNC16(dst, src) \
    asm volatile("cp.async.ca.shared.global [%0], [%1], 16;" :: "r"(dst), "l"(src))
#define CPCOMMIT() asm volatile("cp.async.commit_group;" ::: "memory")
#define CPWAIT0()  asm volatile("cp.async.wait_group 0;" ::: "memory")

// ---------------------------------------------------------------------------
// Kernel N: fp16 1-pass mma.sync node kernel; A and B staged purely via
// cp.async from pre-converted fp16 images. (Identical to R14's passing one.)
// Block = 256 threads (8 warps), M=64 nodes, N=256, K=256 in 4 chunks of 64.
// Warp tile M32 x N64; A+B double-buffered; register epilogue.
//
// SMEM/CTA (93,184 B -> 2 CTAs/SM):
//   A bufs [2 buf][64 rows][72 halfs]  @ 0        (18,432)
//   B bufs [2 buf][256 rows][72 halfs] @ 18,432   (73,728)
//   s_bl [256] f32                     @ 92,160
//   epilogue overlays: s_part 16K @0; s_wh @16,384; s_bh @33,792
// ---------------------------------------------------------------------------
#define AST     144           // bytes per smem row (64 halfs + 16B pad)
#define A_IMG   9216          // 64*144
#define B_OFF   18432
#define B_IMG   36864         // 256*144
#define OFF_BL  92160
#define SMEM_DYN 93184
#define E_WH  16384
#define E_BH  33792

__global__ __launch_bounds__(256, 2) void node_mma_kernel(
    const float* __restrict__ wp, const float* __restrict__ bp,
    const float* __restrict__ ws, const float* __restrict__ bs,
    const float* __restrict__ bl,
    float* __restrict__ out)
{
    extern __shared__ float4 smem4[];
    char* smem = (char*)smem4;
    const uint32_t sb = smem_u32(smem);
    float* s_bl = (float*)(smem + OFF_BL);

    const int t    = threadIdx.x;
    const int w    = t >> 5;
    const int lane = t & 31;
    const int lq   = lane >> 2;
    const int lr   = (lane & 3) * 2;
    const long long base = (long long)blockIdx.x * 64;

    if (t < 256) s_bl[t] = bl[t];

    const int m0    = (w & 1) * 32;    // 2 M-strips
    const int nbase = (w >> 1) * 64;   // 4 N-strips

    float acc[64];
#pragma unroll
    for (int i = 0; i < 64; i++) acc[i] = 0.f;

    // ---- staging helpers (k=64 chunks), all cp.async ----
    auto stageB = [&](int c, int buf) {   // 256 rows x 128B
        const char* gs = (const char*)&g_Wh[0];
#pragma unroll
        for (int it = 0; it < 8; it++) {
            int i = t + it * 256;         // 0..2047
            int n = i >> 3, q = i & 7;
            uint32_t dst = sb + B_OFF + buf * B_IMG + n * AST + q * 16;
            CPASYNC16(dst, gs + n * 512 + c * 128 + q * 16);
        }
    };
    auto stageA = [&](int c, int buf) {   // 64 rows x 128B
        const __half* gsrc = (c < 2) ? g_aggh : g_xh;
        int koff = (c & 1) * 64;
#pragma unroll
        for (int it = 0; it < 2; it++) {
            int i = t + it * 256;         // 0..511
            int m = i >> 3, q = i & 7;
            long long node = base + m;
            if (node >= N_NODES) node = N_NODES - 1;
            uint32_t dst = sb + buf * A_IMG + m * AST + q * 16;
            CPASYNC16(dst, (const char*)(gsrc + node * D_IN + koff) + q * 16);
        }
    };

    // ---- prologue: chunk 0 into buffer 0 ----
    stageB(0, 0);
    stageA(0, 0);
    CPCOMMIT();
    CPWAIT0();
    __syncthreads();

    const int tt    = lane >> 3;
    const int arow  = ((tt & 1) * 8) + (lane & 7);
    const int acol2 = ((tt >> 1) * 8) * 2;

    // ---- mainloop: 4 chunks, DMA for c+1 overlaps MMAs of c ----
    for (int c = 0; c < 4; c++) {
        int cur = c & 1, nxt = cur ^ 1;
        if (c < 3) {
            stageB(c + 1, nxt);
            stageA(c + 1, nxt);
            CPCOMMIT();
        }

        const uint32_t Ab = sb + cur * A_IMG;
        const uint32_t Bb = sb + B_OFF + cur * B_IMG;
#pragma unroll
        for (int ks = 0; ks < 4; ks++) {
            int kb = ks * 32;             // 16 halfs = 32B per k-step
            uint32_t a0[4], a1[4], b[4][4];
            uint32_t ad = Ab + (m0 + arow) * AST + kb + acol2;
            LDSM4(a0[0], a0[1], a0[2], a0[3], ad);
            LDSM4(a1[0], a1[1], a1[2], a1[3], ad + 16 * AST);
#pragma unroll
            for (int j = 0; j < 4; j++) {
                uint32_t bd = Bb + (nbase + j * 16 + arow) * AST + kb + acol2;
                LDSM4(b[j][0], b[j][1], b[j][2], b[j][3], bd);
            }
#pragma unroll
            for (int j = 0; j < 4; j++) {
                int nt0 = j * 2, nt1 = j * 2 + 1;
                mma_f16(acc + nt0 * 4,      a0, b[j][0], b[j][2]);
                mma_f16(acc + nt1 * 4,      a0, b[j][1], b[j][3]);
                mma_f16(acc + 32 + nt0 * 4, a1, b[j][0], b[j][2]);
                mma_f16(acc + 32 + nt1 * 4, a1, b[j][1], b[j][3]);
            }
        }
        if (c < 3) CPWAIT0();
        __syncthreads();
    }

    // ---- epilogue: overlay A/B region (register-resident heads) ----
    float* s_part = (float*)smem;              // [4 nstrip][64 m][16]
    float* s_wh   = (float*)(smem + E_WH);     // [256][17]
    float* s_bh   = (float*)(smem + E_BH);

    for (int i = t; i < 13 * 256; i += 256) {
        int j = i & 255, cc = i >> 8;
        s_wh[j * 17 + cc] = (cc < 7) ? wp[j * 7 + cc] : ws[j * 6 + (cc - 7)];
    }
    if (t < 16) s_bh[t] = (t < 7) ? bp[t] : (t < 13 ? bs[t - 7] : 0.f);
    __syncthreads();

    const int nstrip = w >> 1;
#pragma unroll
    for (int mi = 0; mi < 2; mi++) {
        float pr0[13], pr1[13];
#pragma unroll
        for (int cc = 0; cc < 13; cc++) { pr0[cc] = 0.f; pr1[cc] = 0.f; }
#pragma unroll
        for (int nt = 0; nt < 8; nt++) {
            int col0 = nbase + nt * 8 + lr;
            float b0 = s_bl[col0], b1 = s_bl[col0 + 1];
            const float* d = acc + mi * 32 + nt * 4;
            float h00 = fmaxf(d[0] + b0, 0.f), h01 = fmaxf(d[1] + b1, 0.f);
            float h10 = fmaxf(d[2] + b0, 0.f), h11 = fmaxf(d[3] + b1, 0.f);
            const float* w0 = s_wh + col0 * 17;
            const float* w1 = w0 + 17;
#pragma unroll
            for (int cc = 0; cc < 13; cc++) {
                float wa = w0[cc], wb = w1[cc];
                pr0[cc] = fmaf(h00, wa, fmaf(h01, wb, pr0[cc]));
                pr1[cc] = fmaf(h10, wa, fmaf(h11, wb, pr1[cc]));
            }
        }
#pragma unroll
        for (int cc = 0; cc < 13; cc++) {
            pr0[cc] += __shfl_xor_sync(0xffffffff, pr0[cc], 1);
            pr0[cc] += __shfl_xor_sync(0xffffffff, pr0[cc], 2);
            pr1[cc] += __shfl_xor_sync(0xffffffff, pr1[cc], 1);
            pr1[cc] += __shfl_xor_sync(0xffffffff, pr1[cc], 2);
        }
        if ((lane & 3) == 0) {
            int r = m0 + mi * 16 + lq;
#pragma unroll
            for (int cc = 0; cc < 13; cc++) {
                s_part[nstrip * 1024 + r * 16 + cc]       = pr0[cc];
                s_part[nstrip * 1024 + (r + 8) * 16 + cc] = pr1[cc];
            }
        }
    }
    __syncthreads();

    // final reduce + log_softmax + writeout
    if (t < 64) {
        long long node = base + t;
        if (node < N_NODES) {
            float o[13];
#pragma unroll
            for (int cc = 0; cc < 13; cc++) {
                o[cc] = s_bh[cc] + s_part[t * 16 + cc] + s_part[1024 + t * 16 + cc]
                      + s_part[2048 + t * 16 + cc] + s_part[3072 + t * 16 + cc];
            }
            float mx = o[0];
#pragma unroll
            for (int cc = 1; cc < 7; cc++) mx = fmaxf(mx, o[cc]);
            float s = 0.f;
#pragma unroll
            for (int cc = 0; cc < 7; cc++) s += __expf(o[cc] - mx);
            float lse = mx + __logf(s);
#pragma unroll
            for (int cc = 0; cc < 7; cc++) out[node * 7 + cc] = o[cc] - lse;

            mx = o[7];
#pragma unroll
            for (int cc = 8; cc < 13; cc++) mx = fmaxf(mx, o[cc]);
            s = 0.f;
#pragma unroll
            for (int cc = 7; cc < 13; cc++) s += __expf(o[cc] - mx);
            lse = mx + __logf(s);
            float* out2 = out + (long long)N_NODES * 7;
#pragma unroll
            for (int cc = 0; cc < 6; cc++) out2[node * 6 + cc] = o[7 + cc] - lse;
        }
    }
}

// ---------------------------------------------------------------------------
extern "C" void kernel_launch(void* const* d_in, const int* in_sizes, int n_in,
                              void* d_out, int out_size) {
    const float* x  = (const float*)d_in[0];
    const int*   ei = (const int*)d_in[1];
    const float* wl = (const float*)d_in[2];
    const float* bl = (const float*)d_in[3];
    const float* wr = (const float*)d_in[4];
    const float* wp = (const float*)d_in[5];
    const float* bp = (const float*)d_in[6];
    const float* ws = (const float*)d_in[7];
    const float* bs = (const float*)d_in[8];
    float* out = (float*)d_out;

    cudaFuncSetAttribute(node_mma_kernel,
                         cudaFuncAttributeMaxDynamicSharedMemorySize, SMEM_DYN);

    init_kernel<<<12854, 256>>>(x, wl, wr);
    hist_kernel<<<(N_EDGES + 255) / 256, 256>>>(ei);
    scan_block_kernel<<<NBLK, 256>>>();
    scan_add_kernel<<<NBLK, 256>>>();
    scatter_kernel<<<(N_EDGES + 255) / 256, 256>>>(ei);
    gather_kernel<<<N_NODES / 8, 256>>>();

    int node_blocks = (N_NODES + 63) / 64;   // 1563
    node_mma_kernel<<<node_blocks, 256, SMEM_DYN>>>(wp, bp, ws, bs, bl, out);
}